// round 6
// baseline (speedup 1.0000x reference)
#include <cuda_runtime.h>
#include <cuda_bf16.h>
#include <math.h>

// Problem constants (fixed shapes for RoIPointPool3d_23845658427905)
#define BB   4
#define NPTS 16384
#define MM   128
#define CF   128
#define SS   512
#define OUTF (3 + CF)   // 131 floats per pooled row
#define BPC  4          // boxes per mask CTA
#define PSPL 4          // point-range splits per box group
#define PPS  (NPTS / PSPL)   // 4096 points per split
#define GROWS 128       // rows per gather CTA (4 CTAs per box)
#define STG_ROWS 32     // rows per smem stage

// Scratch (device globals — no allocation allowed)
__device__ int g_table[BB * MM * PSPL * SS]; // per (box, split): ordered in-box indices
__device__ int g_cnt[BB * MM * PSPL];        // per (box, split): in-box counts

// ---------------------------------------------------------------------------
// Kernel 1: fused box-prep (fp64 sincos, fast-math immune) + membership +
// ordered compaction, with a conservative radius cull: rotation preserves
// the 2D norm, so a point inside the rotated rectangle must satisfy
// sx^2+sy^2 < hx^2+hy^2; we ballot on d2 < 1.001*(hx^2+hy^2) (slack >> ulp,
// can never falsely cull) and skip the exact test when no lane survives.
// ---------------------------------------------------------------------------
__global__ __launch_bounds__(512) void roipool_mask_kernel(
    const float* __restrict__ points,   // (B, N, 3)
    const float* __restrict__ boxes)    // (B, M, 7)
{
    const int split = blockIdx.x & (PSPL - 1);
    const int quad  = blockIdx.x >> 2;       // 0..127
    const int bm0   = quad * BPC;            // first box of the quad
    const int b     = bm0 >> 7;              // / MM

    __shared__ float    sprep[BPC * 8];      // cx, cy, czc, hx, hy, hz, ca, sa
    __shared__ unsigned sball[BPC][16][8];
    __shared__ int      wtot[BPC][16];

    const int tid  = threadIdx.x;
    const int lane = tid & 31;
    const int w    = tid >> 5;

    if (w == 0 && lane < BPC) {
        const int q = lane;
        const float* bx = boxes + (size_t)(bm0 + q) * 7;
        const float r0 = bx[0], r1 = bx[1], r2 = bx[2];
        const float r3 = bx[3], r4 = bx[4], r5 = bx[5], r6 = bx[6];
        double sv, cv;
        sincos(-(double)r6, &sv, &cv);
        float* o = sprep + q * 8;
        o[0] = r0;
        o[1] = r1;
        o[2] = __fadd_rn(r2, __fmul_rn(0.5f, r5));
        o[3] = __fmul_rn(0.5f, r3);
        o[4] = __fmul_rn(0.5f, r4);
        o[5] = __fmul_rn(0.5f, r5);
        o[6] = (float)cv;
        o[7] = (float)sv;
    }
    __syncthreads();

    float cx[BPC], cy[BPC], cz[BPC], hx[BPC], hy[BPC], hz[BPC], ca[BPC], sa[BPC], r2c[BPC];
    #pragma unroll
    for (int q = 0; q < BPC; q++) {
        cx[q] = sprep[q * 8 + 0]; cy[q] = sprep[q * 8 + 1];
        cz[q] = sprep[q * 8 + 2]; hx[q] = sprep[q * 8 + 3];
        hy[q] = sprep[q * 8 + 4]; hz[q] = sprep[q * 8 + 5];
        ca[q] = sprep[q * 8 + 6]; sa[q] = sprep[q * 8 + 7];
        r2c[q] = 1.001f * (hx[q] * hx[q] + hy[q] * hy[q]);   // conservative cull radius^2
    }

    const int base_local = split * PPS + w * 256;          // batch-relative
    const float* pb = points + ((size_t)b * NPTS + base_local) * 3;

    int cnt[BPC];
    #pragma unroll
    for (int q = 0; q < BPC; q++) cnt[q] = 0;

    for (int j = 0; j < 8; j++) {
        const int i3 = (j * 32 + lane) * 3;
        const float x = pb[i3 + 0];
        const float y = pb[i3 + 1];
        const float z = pb[i3 + 2];
        #pragma unroll
        for (int q = 0; q < BPC; q++) {
            const float sx = __fsub_rn(x, cx[q]);
            const float sy = __fsub_rn(y, cy[q]);
            const float d2 = __fmaf_rn(sy, sy, __fmul_rn(sx, sx));   // cull only
            const unsigned maybe = __ballot_sync(0xffffffffu, d2 < r2c[q]);
            if (maybe == 0u) {
                if (lane == 0) sball[q][w][j] = 0u;
                continue;
            }
            // exact membership test (bit-identical to the proven path)
            const float lx = __fsub_rn(__fmul_rn(sx, ca[q]), __fmul_rn(sy, sa[q]));
            const float ly = __fadd_rn(__fmul_rn(sx, sa[q]), __fmul_rn(sy, ca[q]));
            const float zd = __fsub_rn(z, cz[q]);
            const bool m = (fabsf(zd) <= hz[q]) && (fabsf(lx) < hx[q]) && (fabsf(ly) < hy[q]);
            const unsigned ball = __ballot_sync(0xffffffffu, m);
            if (lane == 0) sball[q][w][j] = ball;
            cnt[q] += __popc(ball);
        }
    }
    if (lane == 0) {
        #pragma unroll
        for (int q = 0; q < BPC; q++) wtot[q][w] = cnt[q];
    }
    __syncthreads();

    const unsigned lt = (1u << lane) - 1u;
    #pragma unroll
    for (int q = 0; q < BPC; q++) {
        int run = 0;
        #pragma unroll
        for (int v = 0; v < 16; v++)
            if (v < w) run += wtot[q][v];
        int* tbl = g_table + (size_t)((bm0 + q) * PSPL + split) * SS;
        #pragma unroll
        for (int j = 0; j < 8; j++) {
            const unsigned ball = sball[q][w][j];
            const int pre = __popc(ball & lt);
            if (((ball >> lane) & 1u) && (run + pre) < SS)
                tbl[run + pre] = base_local + j * 32 + lane;
            run += __popc(ball);
        }
    }

    if (tid < BPC) {
        int tot = 0;
        #pragma unroll
        for (int v = 0; v < 16; v++) tot += wtot[tid][v];
        g_cnt[(bm0 + tid) * PSPL + split] = tot;
    }
}

// ---------------------------------------------------------------------------
// Kernel 2: gather — smem-staged flat-slab writes.
// 4 CTAs per box (2048 CTAs, 256 threads). Each CTA emits 128 rows in 4
// stages of 32 rows: feature rows loaded with ONE LDG.128 per lane (aligned,
// 4 wavefronts/row), placed into a 32x131 smem stage already in final layout
// (the +3 shift happens at STS time), then the stage drains as a flat,
// perfectly-coalesced float4 stream (LDS.128 + STG.128, 131 wavefronts for
// 16.4 KB vs ~288 for the old per-row misaligned stores).
// ---------------------------------------------------------------------------
__global__ __launch_bounds__(256) void roipool_gather_kernel(
    const float* __restrict__ points,   // (B, N, 3)
    const float* __restrict__ feats,    // (B, N, C)
    float* __restrict__ out,            // (B, M, S, 131)
    float* __restrict__ flags)          // (B, M)
{
    const int cid     = blockIdx.x;     // 0 .. 4*B*M-1
    const int bm      = cid >> 2;
    const int quarter = cid & 3;
    const int b       = bm >> 7;        // / MM
    const int tid  = threadIdx.x;
    const int lane = tid & 31;
    const int w    = tid >> 5;          // 0..7

    __shared__ __align__(16) float sstage[STG_ROWS * OUTF];  // 32*131 floats
    __shared__ int sidx[GROWS];
    __shared__ int pf[4];
    __shared__ int scnt;

    if (tid == 0) {
        const int c0 = g_cnt[bm * PSPL + 0];
        const int c1 = g_cnt[bm * PSPL + 1];
        const int c2 = g_cnt[bm * PSPL + 2];
        const int c3 = g_cnt[bm * PSPL + 3];
        pf[0] = 0; pf[1] = c0; pf[2] = c0 + c1; pf[3] = c0 + c1 + c2;
        const int tot = c0 + c1 + c2 + c3;
        scnt = tot;
        if (quarter == 0) flags[bm] = (tot == 0) ? 1.0f : 0.0f;
    }
    __syncthreads();
    const int cnt = scnt;

    const int rbase = quarter * GROWS;              // first row of this CTA
    float* obox = out + (size_t)bm * SS * OUTF;

    if (cnt == 0) {
        const float4 zz = make_float4(0.f, 0.f, 0.f, 0.f);
        float4* o4 = (float4*)(obox + (size_t)rbase * OUTF);   // 128*131 % 4 == 0
        for (int i = tid; i < GROWS * OUTF / 4; i += 256) __stcs(&o4[i], zz);
        return;
    }

    // resolve wrap-around indices for this CTA's 128 rows
    if (tid < GROWS) {
        const int s = rbase + tid;
        const int j = s % cnt;
        const int p = (j >= pf[3]) ? 3 : (j >= pf[2]) ? 2 : (j >= pf[1]) ? 1 : 0;
        sidx[tid] = g_table[(size_t)(bm * PSPL + p) * SS + (j - pf[p])];
    }
    __syncthreads();

    const float* pbat = points + (size_t)b * NPTS * 3;
    const float* fbat = feats  + (size_t)b * NPTS * CF;

    for (int st = 0; st < GROWS / STG_ROWS; st++) {
        // fill stage: warp w handles stage-local rows w*4 .. w*4+3
        #pragma unroll
        for (int r = 0; r < 4; r++) {
            const int lrow = w * 4 + r;                       // 0..31 within stage
            const int idx  = sidx[st * STG_ROWS + lrow];
            const float4 f4 = ((const float4*)(fbat + (size_t)idx * CF))[lane];
            float* srow = sstage + lrow * OUTF;
            const int c = 3 + lane * 4;
            srow[c + 0] = f4.x;
            srow[c + 1] = f4.y;
            srow[c + 2] = f4.z;
            srow[c + 3] = f4.w;
            if (lane < 3) srow[lane] = pbat[(size_t)idx * 3 + lane];
        }
        __syncthreads();

        // drain stage as flat float4 stream (perfectly coalesced)
        const float4* s4 = (const float4*)sstage;
        float4* d4 = (float4*)(obox + (size_t)(rbase + st * STG_ROWS) * OUTF);
        #pragma unroll
        for (int i = 0; i < (STG_ROWS * OUTF / 4 + 255) / 256; i++) {
            const int k = i * 256 + tid;
            if (k < STG_ROWS * OUTF / 4) __stcs(&d4[k], s4[k]);
        }
        __syncthreads();
    }
}

// ---------------------------------------------------------------------------
extern "C" void kernel_launch(void* const* d_in, const int* in_sizes, int n_in,
                              void* d_out, int out_size)
{
    const float* points = (const float*)d_in[0];   // (B, N, 3)
    const float* feats  = (const float*)d_in[1];   // (B, N, C)
    const float* boxes  = (const float*)d_in[2];   // (B, M, 7)

    float* out   = (float*)d_out;
    float* flags = out + (size_t)BB * MM * SS * OUTF;  // empty flags appended

    roipool_mask_kernel<<<(BB * MM / BPC) * PSPL, 512>>>(points, boxes);
    roipool_gather_kernel<<<BB * MM * 4, 256>>>(points, feats, out, flags);
}